// round 3
// baseline (speedup 1.0000x reference)
#include <cuda_runtime.h>
#include <cstdint>

// Batched outer product: out[i, j*K + l] = x[i,j] * y[i,l]
// n=4096, m=256, k=256 → each output row = 65536 f32 = 8192 float8.
// Pure store-bandwidth kernel. 256-bit stores + shfl-broadcast x, no smem.

static constexpr int M = 256;
static constexpr int K = 256;
static constexpr int ROW_F8 = (M * K) / 8;   // 8192 float8 per output row

__global__ __launch_bounds__(256, 8)
void omul_kernel(const float* __restrict__ x,
                 const float* __restrict__ y,
                 float* __restrict__ out)
{
    const int row  = blockIdx.x;
    const int t    = threadIdx.x;
    const int w    = t >> 5;     // warp id 0..7
    const int lane = t & 31;

    // y chunk for this thread is fixed: float8 index (idx & 31) == (t & 31).
    const float4* y4 = reinterpret_cast<const float4*>(y + (size_t)row * K);
    const float4 ya = y4[lane * 2 + 0];
    const float4 yb = y4[lane * 2 + 1];

    // Lane l pre-holds x[l*8 + w]; iteration i broadcasts lane i's value,
    // which equals x[i*8 + w] — exactly the j-index this warp needs.
    const float xreg = x[(size_t)row * M + lane * 8 + w];

    float* o = out + (size_t)row * (M * K);

    #pragma unroll 8
    for (int i = 0; i < 32; i++) {
        const float xv = __shfl_sync(0xFFFFFFFFu, xreg, i);
        const int idx = i * 256 + t;            // float8 index within row
        float* p = o + (size_t)idx * 8;

        const float r0 = xv * ya.x, r1 = xv * ya.y, r2 = xv * ya.z, r3 = xv * ya.w;
        const float r4 = xv * yb.x, r5 = xv * yb.y, r6 = xv * yb.z, r7 = xv * yb.w;

        asm volatile(
            "st.global.cs.v8.b32 [%0], {%1, %2, %3, %4, %5, %6, %7, %8};"
            :: "l"(p),
               "r"(__float_as_uint(r0)), "r"(__float_as_uint(r1)),
               "r"(__float_as_uint(r2)), "r"(__float_as_uint(r3)),
               "r"(__float_as_uint(r4)), "r"(__float_as_uint(r5)),
               "r"(__float_as_uint(r6)), "r"(__float_as_uint(r7))
            : "memory");
    }
}

extern "C" void kernel_launch(void* const* d_in, const int* in_sizes, int n_in,
                              void* d_out, int out_size)
{
    const float* x = (const float*)d_in[0];
    const float* y = (const float*)d_in[1];
    float* out = (float*)d_out;

    const int n = in_sizes[0] / M;  // 4096 rows
    omul_kernel<<<n, 256>>>(x, y, out);
}